// round 10
// baseline (speedup 1.0000x reference)
#include <cuda_runtime.h>
#include <cstdint>

// ---------------- problem constants ----------------
#define BATCH 256
#define HW    147456            // 384*384 px per sample
#define NB    4096              // coarse histogram bins (bin = q >> 4)
#define QSCALE 65535.0f

// target order-statistic ranks (0-based): q*(n-1) = 14745.5 / 132709.5
#define KL 14745
#define KH 132709

#define TPB   1024
#define BPS   4                  // blocks per sample
#define PXB   (HW / BPS)         // 36864 px per block
#define ITER  (PXB / (TPB * 4))  // 9 quartets per thread
#define WPT   (ITER * 2)         // 18 packed words per thread (36 px)

// ---------------- device scratch (static, allocation-free, zero-init) -------
__device__ int    g_hist[BATCH * NB];   // self-cleaned by phase-1 selector
__device__ int    g_sub[BATCH][64];     // sub-histograms, zeroed by phase-2 selector
__device__ int    g_c1[BATCH], g_c2[BATCH], g_fin[BATCH];
__device__ int    g_r1[BATCH], g_r2[BATCH];
__device__ int    g_windat[BATCH][6];   // loMin, loMax, hiMin, hiMax, cum0, cum1
__device__ float2 g_ab[BATCH];          // loQ, invQ

__global__ void __launch_bounds__(TPB) mono(const float* __restrict__ x,
                                            float* __restrict__ out) {
    __shared__ int sh[NB];
    __shared__ int s_warp[32];
    __shared__ int s_role1, s_role2;
    __shared__ int s_sub[64];

    const int s     = blockIdx.x >> 2;
    const int chunk = blockIdx.x & (BPS - 1);
    const int t     = threadIdx.x;
    const int lane  = t & 31;
    const int wid   = t >> 5;

    // ================= phase 1: stream x, quantize to regs, histogram =======
    for (int i = t; i < NB; i += TPB) sh[i] = 0;
    __syncthreads();

    const int base = s * HW + chunk * PXB;
    const float4* __restrict__ xin = (const float4*)x;
    const float third = 1.0f / 3.0f;
    uint32_t rq[WPT];

#pragma unroll 3
    for (int it = 0; it < ITER; ++it) {
        int p  = base + it * (TPB * 4) + t * 4;
        int f4 = (p * 3) >> 2;
        float4 a = __ldcs(xin + f4 + 0);
        float4 b = __ldcs(xin + f4 + 1);
        float4 c = __ldcs(xin + f4 + 2);

        uint32_t q0 = min((uint32_t)((a.x + a.y + a.z) * third * QSCALE + 0.5f), 65535u);
        uint32_t q1 = min((uint32_t)((a.w + b.x + b.y) * third * QSCALE + 0.5f), 65535u);
        uint32_t q2 = min((uint32_t)((b.z + b.w + c.x) * third * QSCALE + 0.5f), 65535u);
        uint32_t q3 = min((uint32_t)((c.y + c.z + c.w) * third * QSCALE + 0.5f), 65535u);

        rq[2 * it]     = q0 | (q1 << 16);
        rq[2 * it + 1] = q2 | (q3 << 16);

        atomicAdd(&sh[q0 >> 4], 1);
        atomicAdd(&sh[q1 >> 4], 1);
        atomicAdd(&sh[q2 >> 4], 1);
        atomicAdd(&sh[q3 >> 4], 1);
    }
    __syncthreads();

    int* gh = &g_hist[s * NB];
    for (int i = t; i < NB; i += TPB) {
        int v = sh[i];
        if (v) atomicAdd(&gh[i], v);
    }
    __threadfence();

    if (t == 0) s_role1 = atomicAdd(&g_c1[s], 1);
    __syncthreads();

    // ======== phase 1b: last-arriving block scans hist, publishes windows ====
    if (s_role1 == BPS - 1) {
        __threadfence();   // acquire all blocks' hist flushes
        int4 cw = *(int4*)(gh + 4 * t);
        *(int4*)(gh + 4 * t) = make_int4(0, 0, 0, 0);   // self-clean for replay
        int cnt[4] = {cw.x, cw.y, cw.z, cw.w};
        int local = cnt[0] + cnt[1] + cnt[2] + cnt[3];

        int v = local;
#pragma unroll
        for (int o = 1; o < 32; o <<= 1) {
            int n = __shfl_up_sync(0xFFFFFFFFu, v, o);
            if (lane >= o) v += n;
        }
        if (lane == 31) s_warp[wid] = v;
        __syncthreads();
        if (wid == 0) {
            int wv = s_warp[lane];
#pragma unroll
            for (int o = 1; o < 32; o <<= 1) {
                int n = __shfl_up_sync(0xFFFFFFFFu, wv, o);
                if (lane >= o) wv += n;
            }
            s_warp[lane] = wv;
        }
        __syncthreads();
        int cum = (v - local) + (wid ? s_warp[wid - 1] : 0);

        const int targets[4] = {KL, KL + 1, KH, KH + 1};
#pragma unroll
        for (int i = 0; i < 4; i++) {
            int c = cnt[i];
            int bin = 4 * t + i;
#pragma unroll
            for (int k = 0; k < 4; k++) {
                int r = targets[k];
                if (cum <= r && r < cum + c) {
                    if (k == 0) { g_windat[s][0] = bin; g_windat[s][4] = cum; }
                    if (k == 1) { g_windat[s][1] = bin; }
                    if (k == 2) { g_windat[s][2] = bin; g_windat[s][5] = cum; }
                    if (k == 3) { g_windat[s][3] = bin; }
                }
            }
            cum += c;
        }
        __syncthreads();
        if (t == 0) { __threadfence(); ((volatile int*)g_r1)[s] = 1; }
    }

    if (t == 0) { while (((volatile int*)g_r1)[s] == 0) __nanosleep(64); }
    __syncthreads();
    __threadfence();   // acquire window data

    const int loMin = g_windat[s][0], loMax = g_windat[s][1];
    const int hiMin = g_windat[s][2], hiMax = g_windat[s][3];

    // ================= phase 2: scatter window hits to sub-histogram =========
#pragma unroll
    for (int w = 0; w < WPT; w++) {
        uint32_t pk = rq[w];
        uint32_t qa = pk & 0xFFFFu, qb = pk >> 16;
        int ba = (int)(qa >> 4), bb = (int)(qb >> 4);
        if (ba == loMin)      atomicAdd(&g_sub[s][qa & 15], 1);
        else if (ba == loMax) atomicAdd(&g_sub[s][16 + (qa & 15)], 1);
        if (ba == hiMin)      atomicAdd(&g_sub[s][32 + (qa & 15)], 1);
        else if (ba == hiMax) atomicAdd(&g_sub[s][48 + (qa & 15)], 1);
        if (bb == loMin)      atomicAdd(&g_sub[s][qb & 15], 1);
        else if (bb == loMax) atomicAdd(&g_sub[s][16 + (qb & 15)], 1);
        if (bb == hiMin)      atomicAdd(&g_sub[s][32 + (qb & 15)], 1);
        else if (bb == hiMax) atomicAdd(&g_sub[s][48 + (qb & 15)], 1);
    }
    __threadfence();

    if (t == 0) s_role2 = atomicAdd(&g_c2[s], 1);
    __syncthreads();

    // ======== phase 2b: last arriver selects exact quantiles from subs =======
    if (s_role2 == BPS - 1) {
        __threadfence();
        if (t < 64) { s_sub[t] = g_sub[s][t]; }
        __syncthreads();
        if (t < 64) g_sub[s][t] = 0;            // self-clean for replay
        if (t == 0) {
            float vsel[4];
            // lo: group0 = bin loMin (values ascending), group1 = bin loMax
            {
                int t0 = KL - g_windat[s][4];
                int cum = 0;
                int found = 0;
                for (int g = 0; g < 2 && found < 2; g++) {
                    if (g == 1 && loMax == loMin) break;
                    int binv = (g ? loMax : loMin) << 4;
                    for (int i = 0; i < 16 && found < 2; i++) {
                        int c = s_sub[g * 16 + i];
                        if (found == 0 && cum <= t0 && t0 < cum + c) { vsel[0] = (float)(binv + i); found = 1; }
                        if (found <= 1 && cum <= t0 + 1 && t0 + 1 < cum + c) { vsel[1] = (float)(binv + i); found = 2; }
                        cum += c;
                    }
                }
            }
            // hi
            {
                int t0 = KH - g_windat[s][5];
                int cum = 0;
                int found = 0;
                for (int g = 0; g < 2 && found < 2; g++) {
                    if (g == 1 && hiMax == hiMin) break;
                    int binv = (g ? hiMax : hiMin) << 4;
                    for (int i = 0; i < 16 && found < 2; i++) {
                        int c = s_sub[32 + g * 16 + i];
                        if (found == 0 && cum <= t0 && t0 < cum + c) { vsel[2] = (float)(binv + i); found = 1; }
                        if (found <= 1 && cum <= t0 + 1 && t0 + 1 < cum + c) { vsel[3] = (float)(binv + i); found = 2; }
                        cum += c;
                    }
                }
            }
            float loQ = 0.5f * (vsel[0] + vsel[1]);
            float hiQ = 0.5f * (vsel[2] + vsel[3]);
            float rngQ = fmaxf(hiQ - loQ, 1e-6f * QSCALE);
            g_ab[s] = make_float2(loQ, 1.0f / rngQ);
            __threadfence();
            ((volatile int*)g_r2)[s] = 1;
        }
    }

    if (t == 0) { while (((volatile int*)g_r2)[s] == 0) __nanosleep(64); }
    __syncthreads();
    __threadfence();

    float2 ab = g_ab[s];
    const float loQ  = ab.x;
    const float invQ = ab.y;

    // ================= phase 3: normalize from registers, stream out =========
    float4* __restrict__ o4 = (float4*)out;
#pragma unroll
    for (int it = 0; it < ITER; ++it) {
        int p = base + it * (TPB * 4) + t * 4;
        uint32_t p0 = rq[2 * it], p1 = rq[2 * it + 1];
        float4 r;
        r.x = __saturatef(((float)(p0 & 0xFFFFu) - loQ) * invQ);
        r.y = __saturatef(((float)(p0 >> 16)     - loQ) * invQ);
        r.z = __saturatef(((float)(p1 & 0xFFFFu) - loQ) * invQ);
        r.w = __saturatef(((float)(p1 >> 16)     - loQ) * invQ);
        __stcs(o4 + (p >> 2), r);
    }

    // ================= cleanup: last block resets coordination state =========
    __threadfence();
    if (t == 0) {
        int r = atomicAdd(&g_fin[s], 1);
        if (r == BPS - 1) {
            g_c1[s] = 0; g_c2[s] = 0;
            ((volatile int*)g_r1)[s] = 0;
            ((volatile int*)g_r2)[s] = 0;
            __threadfence();
            g_fin[s] = 0;
        }
    }
}

// ---------------- launch ----------------
extern "C" void kernel_launch(void* const* d_in, const int* in_sizes, int n_in,
                              void* d_out, int out_size) {
    const float* x = (const float*)d_in[0];
    float* out = (float*)d_out;

    mono<<<BATCH * BPS, TPB>>>(x, out);
}

// round 11
// speedup vs baseline: 1.3305x; 1.3305x over previous
#include <cuda_runtime.h>
#include <cstdint>

// ---------------- problem constants ----------------
#define BATCH 256
#define HW    147456            // 384*384 px per sample
#define NB    4096              // coarse histogram bins (bin = q >> 4)
#define QSCALE 65535.0f

// target order-statistic ranks (0-based): q*(n-1) = 14745.5 / 132709.5
#define KL 14745
#define KH 132709

// K1 geometry: 4 blocks/sample, 1024 threads, 36 px/thread
#define TPB1   1024
#define BPS1   4
#define PXB1   (HW / BPS1)            // 36864 px per block
#define ITER1  (PXB1 / (TPB1 * 4))    // 9 iterations of 4 px

// K3 geometry: 4 blocks/sample, 1024 threads, 9 uint2/thread
#define TPB3   1024
#define BPS3   4
#define W3     (HW / 4 / BPS3 / TPB3) // 9

// K5 geometry: 9 blocks/sample, 512 threads, 8 float4 (32 px) per thread
#define TPB5   512
#define F4PT   8
#define PXB5   (TPB5 * F4PT * 4)      // 16384 px per block
#define BPS5   (HW / PXB5)            // 9 blocks per sample

// ---------------- device scratch (static, allocation-free, zero-init) -------
__device__ uint32_t g_xq[BATCH * HW / 2];   // packed u16 means, 75 MB
__device__ int      g_hist[BATCH * NB];     // per-sample hist (self-cleaned by k2)
__device__ int      g_windat[BATCH][6];     // loMin, loMax, hiMin, hiMax, cum0, cum1
__device__ int      g_sub[64][BATCH];       // sub-hist, transposed (self-cleaned by k4)
__device__ float2   g_ab[BATCH];            // loQ, invQ

// ---- K1: stream x, channel-mean, quantize u16, write xq, coarse hist -------
__global__ void __launch_bounds__(TPB1) k1_quant_hist(const float* __restrict__ x) {
    __shared__ int sh[NB];
    const int s     = blockIdx.x >> 2;
    const int chunk = blockIdx.x & (BPS1 - 1);
    const int t     = threadIdx.x;

    for (int i = t; i < NB; i += TPB1) sh[i] = 0;
    __syncthreads();

    const int base = s * HW + chunk * PXB1;
    const float4* __restrict__ xin = (const float4*)x;
    const float third = 1.0f / 3.0f;

#pragma unroll 3
    for (int it = 0; it < ITER1; ++it) {
        int p  = base + it * (TPB1 * 4) + t * 4;
        int f4 = (p * 3) >> 2;
        float4 a = __ldcs(xin + f4 + 0);   // stream x: don't pollute L2
        float4 b = __ldcs(xin + f4 + 1);
        float4 c = __ldcs(xin + f4 + 2);

        uint32_t q0 = min((uint32_t)((a.x + a.y + a.z) * third * QSCALE + 0.5f), 65535u);
        uint32_t q1 = min((uint32_t)((a.w + b.x + b.y) * third * QSCALE + 0.5f), 65535u);
        uint32_t q2 = min((uint32_t)((b.z + b.w + c.x) * third * QSCALE + 0.5f), 65535u);
        uint32_t q3 = min((uint32_t)((c.y + c.z + c.w) * third * QSCALE + 0.5f), 65535u);

        uint2 w; w.x = q0 | (q1 << 16); w.y = q2 | (q3 << 16);
        ((uint2*)g_xq)[p >> 2] = w;        // retain in L2 for k3/k5

        atomicAdd(&sh[q0 >> 4], 1);
        atomicAdd(&sh[q1 >> 4], 1);
        atomicAdd(&sh[q2 >> 4], 1);
        atomicAdd(&sh[q3 >> 4], 1);
    }
    __syncthreads();

    int* gh = &g_hist[s * NB];
    for (int i = t; i < NB; i += TPB1) {
        int v = sh[i];
        if (v) atomicAdd(&gh[i], v);
    }
}

// ---- k2: scan hist -> window bins + cums; self-clean hist -------------------
__global__ void __launch_bounds__(1024) k2_scan() {
    __shared__ int s_warp[32];
    const int s = blockIdx.x;
    const int t = threadIdx.x;
    const int lane = t & 31;
    const int wid  = t >> 5;

    int* gh = &g_hist[s * NB];
    int4 cw = *(int4*)(gh + 4 * t);
    *(int4*)(gh + 4 * t) = make_int4(0, 0, 0, 0);   // self-clean for replay
    int cnt[4] = {cw.x, cw.y, cw.z, cw.w};
    int local = cnt[0] + cnt[1] + cnt[2] + cnt[3];

    int v = local;
#pragma unroll
    for (int o = 1; o < 32; o <<= 1) {
        int n = __shfl_up_sync(0xFFFFFFFFu, v, o);
        if (lane >= o) v += n;
    }
    if (lane == 31) s_warp[wid] = v;
    __syncthreads();
    if (wid == 0) {
        int wv = s_warp[lane];
#pragma unroll
        for (int o = 1; o < 32; o <<= 1) {
            int n = __shfl_up_sync(0xFFFFFFFFu, wv, o);
            if (lane >= o) wv += n;
        }
        s_warp[lane] = wv;
    }
    __syncthreads();
    int cum = (v - local) + (wid ? s_warp[wid - 1] : 0);

    const int targets[4] = {KL, KL + 1, KH, KH + 1};
#pragma unroll
    for (int i = 0; i < 4; i++) {
        int c = cnt[i];
        int bin = 4 * t + i;
#pragma unroll
        for (int k = 0; k < 4; k++) {
            int r = targets[k];
            if (cum <= r && r < cum + c) {
                if (k == 0) { g_windat[s][0] = bin; g_windat[s][4] = cum; }
                if (k == 1) { g_windat[s][1] = bin; }
                if (k == 2) { g_windat[s][2] = bin; g_windat[s][5] = cum; }
                if (k == 3) { g_windat[s][3] = bin; }
            }
        }
        cum += c;
    }
}

// ---- k3: stream xq (L2-hot), scatter window hits into global sub-hist ------
__global__ void __launch_bounds__(TPB3) k3_gather() {
    const int s     = blockIdx.x >> 2;
    const int chunk = blockIdx.x & (BPS3 - 1);
    const int t     = threadIdx.x;

    const int loMin = g_windat[s][0], loMax = g_windat[s][1];
    const int hiMin = g_windat[s][2], hiMax = g_windat[s][3];

    const uint2* __restrict__ xq2 =
        (const uint2*)g_xq + (size_t)s * (HW / 4) + chunk * (TPB3 * W3);

#pragma unroll
    for (int k = 0; k < W3; k++) {
        uint2 w = xq2[k * TPB3 + t];
        uint32_t qs[4] = {w.x & 0xFFFFu, w.x >> 16, w.y & 0xFFFFu, w.y >> 16};
#pragma unroll
        for (int i = 0; i < 4; i++) {
            uint32_t q = qs[i];
            int b = (int)(q >> 4);
            if (b == loMin)      atomicAdd(&g_sub[q & 15][s], 1);
            else if (b == loMax) atomicAdd(&g_sub[16 + (q & 15)][s], 1);
            if (b == hiMin)      atomicAdd(&g_sub[32 + (q & 15)][s], 1);
            else if (b == hiMax) atomicAdd(&g_sub[48 + (q & 15)][s], 1);
        }
    }
}

// ---- k4: one thread per sample — walk sub-hist, exact quantiles, clean -----
__global__ void __launch_bounds__(32) k4_select() {
    const int s = blockIdx.x * 32 + threadIdx.x;
    if (s >= BATCH) return;

    int sub[64];
#pragma unroll
    for (int i = 0; i < 64; i++) { sub[i] = g_sub[i][s]; g_sub[i][s] = 0; }

    const int loMin = g_windat[s][0], loMax = g_windat[s][1];
    const int hiMin = g_windat[s][2], hiMax = g_windat[s][3];

    float vsel[4];
    // lo quantile: ranks KL, KL+1
    {
        int t0 = KL - g_windat[s][4];
        int cum = 0, found = 0;
        for (int g = 0; g < 2 && found < 2; g++) {
            if (g == 1 && loMax == loMin) break;
            int binv = (g ? loMax : loMin) << 4;
            for (int i = 0; i < 16 && found < 2; i++) {
                int c = sub[g * 16 + i];
                if (found == 0 && cum <= t0 && t0 < cum + c) { vsel[0] = (float)(binv + i); found = 1; }
                if (found <= 1 && cum <= t0 + 1 && t0 + 1 < cum + c) { vsel[1] = (float)(binv + i); found = 2; }
                cum += c;
            }
        }
    }
    // hi quantile: ranks KH, KH+1
    {
        int t0 = KH - g_windat[s][5];
        int cum = 0, found = 0;
        for (int g = 0; g < 2 && found < 2; g++) {
            if (g == 1 && hiMax == hiMin) break;
            int binv = (g ? hiMax : hiMin) << 4;
            for (int i = 0; i < 16 && found < 2; i++) {
                int c = sub[32 + g * 16 + i];
                if (found == 0 && cum <= t0 && t0 < cum + c) { vsel[2] = (float)(binv + i); found = 1; }
                if (found <= 1 && cum <= t0 + 1 && t0 + 1 < cum + c) { vsel[3] = (float)(binv + i); found = 2; }
                cum += c;
            }
        }
    }

    float loQ = 0.5f * (vsel[0] + vsel[1]);
    float hiQ = 0.5f * (vsel[2] + vsel[3]);
    float rngQ = fmaxf(hiQ - loQ, 1e-6f * QSCALE);
    g_ab[s] = make_float2(loQ, 1.0f / rngQ);
}

// ---- k5: normalize + clip; xq read mostly L2-hot, streamed output ----------
__global__ void __launch_bounds__(TPB5) k5_norm(float* __restrict__ out) {
    const int s     = blockIdx.x / BPS5;
    const int chunk = blockIdx.x % BPS5;
    const int t     = threadIdx.x;

    float2 ab = g_ab[s];
    const float loQ  = ab.x;
    const float invQ = ab.y;

    const uint2* __restrict__ xq2 =
        (const uint2*)g_xq + (size_t)s * (HW / 4) + chunk * (TPB5 * F4PT);
    float4* __restrict__ o4 =
        (float4*)out + (size_t)s * (HW / 4) + chunk * (TPB5 * F4PT);

#pragma unroll
    for (int k = 0; k < F4PT; k++) {
        uint2 w = __ldcs(xq2 + k * TPB5 + t);   // last use of xq
        float4 r;
        r.x = __saturatef(((float)(w.x & 0xFFFFu) - loQ) * invQ);
        r.y = __saturatef(((float)(w.x >> 16)     - loQ) * invQ);
        r.z = __saturatef(((float)(w.y & 0xFFFFu) - loQ) * invQ);
        r.w = __saturatef(((float)(w.y >> 16)     - loQ) * invQ);
        __stcs(o4 + k * TPB5 + t, r);
    }
}

// ---------------- launch ----------------
extern "C" void kernel_launch(void* const* d_in, const int* in_sizes, int n_in,
                              void* d_out, int out_size) {
    const float* x = (const float*)d_in[0];
    float* out = (float*)d_out;

    k1_quant_hist<<<BATCH * BPS1, TPB1>>>(x);
    k2_scan<<<BATCH, 1024>>>();
    k3_gather<<<BATCH * BPS3, TPB3>>>();
    k4_select<<<(BATCH + 31) / 32, 32>>>();
    k5_norm<<<BATCH * BPS5, TPB5>>>(out);
}